// round 3
// baseline (speedup 1.0000x reference)
#include <cuda_runtime.h>
#include <math.h>

#define B     128
#define H     1024
#define Z     256
#define SRC   64
#define KMAX  48
#define BH    (B*H)
#define X0LD  2336          // [z(256) | k(1) | attn(1024) | pad(31) | h0(1024)]
#define X1LD  2048          // [h0n | h1]
#define G4    4096
#define KS_GATE 4
#define KS_GEN  12
#define KS_OUT  16

// out layout: z[B,K,Z] | mu | sigma | h_f[2,B,H] | c_f[2,B,H]
#define OUT_MU 1572864
#define OUT_SG 3145728
#define OUT_H  4718592
#define OUT_C  4980736

typedef unsigned long long ull;

// ---------------- device scratch ----------------
__device__ __align__(16) float g_x0[B*X0LD];
__device__ __align__(16) float g_x1[B*X1LD];
__device__ __align__(16) float g_xa[B*X1LD];      // [weighted | q]
__device__ __align__(16) float g_c[2*BH];
__device__ __align__(16) float g_w0[G4*X0LD];     // [W_ih0 | 0pad | W_hh0]
__device__ __align__(16) float g_w1[G4*X1LD];     // [W_ih1 | W_hh1]
__device__ __align__(16) float g_wg[1536*H];      // [mu_W ; sigma_W ; attn_W_in]
__device__ __align__(16) float g_part[16*B*G4];   // split-K partials

// ---------------- packed f32x2 (sm_103a FFMA2) ----------------
__device__ __forceinline__ void dfma2(ull& d, ull a, ull b){
    asm("fma.rn.f32x2 %0, %1, %2, %0;" : "+l"(d) : "l"(a), "l"(b));
}
__device__ __forceinline__ float2 funpack(ull v){
    float2 r; asm("mov.b64 {%0,%1}, %2;" : "=f"(r.x), "=f"(r.y) : "l"(v)); return r;
}
__device__ __forceinline__ float sigm(float x){ return 1.f/(1.f+expf(-x)); }

// ---------------- 128x128-tile split-K GEMM, zero-pack FFMA2 inner loop -------
// Partials to g_part[(z*128+m)*4096 + n0+n]. grid=(N/128, KS). K mult of 8.
__global__ __launch_bounds__(256) void gemm128(
    const float* __restrict__ A, int lda,
    const float* __restrict__ W, int ldw, int K)
{
    __shared__ __align__(16) float  As[2][8][128];    // 4KB per buf
    __shared__ __align__(16) float2 Ws[2][8][128];    // 8KB per buf (duplicated)
    const int t  = threadIdx.x;
    const int n0 = blockIdx.x << 7;
    const int z  = blockIdx.y, KS = gridDim.y;
    const int NC = K >> 3;                 // 8-k chunks
    const int tm = (t >> 4) << 3;          // 8 m rows (as 4 pairs)
    const int tn = (t & 15) << 3;          // 8 n cols
    const int lr = t >> 1;                 // loader row 0..127
    const int lk = (t & 1) << 2;           // loader k offset 0/4

    const float* Aptr = A + (size_t)lr * lda + lk;
    const float* Wptr = W + (size_t)(n0 + lr) * ldw + lk;

    ull acc[4][8];
#pragma unroll
    for (int i=0;i<4;i++)
#pragma unroll
        for (int j=0;j<8;j++) acc[i][j]=0ull;

    float4 ar, wr;
    int c = z;
    { int ko = c<<3; ar = *(const float4*)(Aptr+ko); wr = *(const float4*)(Wptr+ko); }
    // stage chunk c into buf 0
    As[0][lk+0][lr]=ar.x; As[0][lk+1][lr]=ar.y; As[0][lk+2][lr]=ar.z; As[0][lk+3][lr]=ar.w;
    Ws[0][lk+0][lr]=make_float2(wr.x,wr.x); Ws[0][lk+1][lr]=make_float2(wr.y,wr.y);
    Ws[0][lk+2][lr]=make_float2(wr.z,wr.z); Ws[0][lk+3][lr]=make_float2(wr.w,wr.w);
    c += KS;
    bool more = c < NC;
    if (more) { int ko = c<<3; ar = *(const float4*)(Aptr+ko); wr = *(const float4*)(Wptr+ko); }
    __syncthreads();

    int buf = 0;
    while (true) {
        if (more) {
            int nb = buf ^ 1;
            As[nb][lk+0][lr]=ar.x; As[nb][lk+1][lr]=ar.y; As[nb][lk+2][lr]=ar.z; As[nb][lk+3][lr]=ar.w;
            Ws[nb][lk+0][lr]=make_float2(wr.x,wr.x); Ws[nb][lk+1][lr]=make_float2(wr.y,wr.y);
            Ws[nb][lk+2][lr]=make_float2(wr.z,wr.z); Ws[nb][lk+3][lr]=make_float2(wr.w,wr.w);
            int c2 = c + KS;
            bool more2 = c2 < NC;
            if (more2) { int ko = c2<<3; ar = *(const float4*)(Aptr+ko); wr = *(const float4*)(Wptr+ko); }
#pragma unroll
            for (int kk=0;kk<8;kk++){
                ulonglong2 ap0 = *(const ulonglong2*)&As[buf][kk][tm];
                ulonglong2 ap1 = *(const ulonglong2*)&As[buf][kk][tm+4];
                ulonglong2 wq0 = *(const ulonglong2*)&Ws[buf][kk][tn];
                ulonglong2 wq1 = *(const ulonglong2*)&Ws[buf][kk][tn+2];
                ulonglong2 wq2 = *(const ulonglong2*)&Ws[buf][kk][tn+4];
                ulonglong2 wq3 = *(const ulonglong2*)&Ws[buf][kk][tn+6];
                ull am[4] = {ap0.x, ap0.y, ap1.x, ap1.y};
                ull wn[8] = {wq0.x, wq0.y, wq1.x, wq1.y, wq2.x, wq2.y, wq3.x, wq3.y};
#pragma unroll
                for (int mi=0; mi<4; mi++)
#pragma unroll
                    for (int nj=0; nj<8; nj++)
                        dfma2(acc[mi][nj], am[mi], wn[nj]);
            }
            __syncthreads();
            buf ^= 1; c = c2; more = more2;
        } else {
#pragma unroll
            for (int kk=0;kk<8;kk++){
                ulonglong2 ap0 = *(const ulonglong2*)&As[buf][kk][tm];
                ulonglong2 ap1 = *(const ulonglong2*)&As[buf][kk][tm+4];
                ulonglong2 wq0 = *(const ulonglong2*)&Ws[buf][kk][tn];
                ulonglong2 wq1 = *(const ulonglong2*)&Ws[buf][kk][tn+2];
                ulonglong2 wq2 = *(const ulonglong2*)&Ws[buf][kk][tn+4];
                ulonglong2 wq3 = *(const ulonglong2*)&Ws[buf][kk][tn+6];
                ull am[4] = {ap0.x, ap0.y, ap1.x, ap1.y};
                ull wn[8] = {wq0.x, wq0.y, wq1.x, wq1.y, wq2.x, wq2.y, wq3.x, wq3.y};
#pragma unroll
                for (int mi=0; mi<4; mi++)
#pragma unroll
                    for (int nj=0; nj<8; nj++)
                        dfma2(acc[mi][nj], am[mi], wn[nj]);
            }
            break;
        }
    }

    // epilogue: acc[mi][nj] holds (m = tm+2mi, m+1) x (n = tn+nj)
    float* P = g_part + ((size_t)(z*128 + tm))*4096 + n0 + tn;
#pragma unroll
    for (int mi=0; mi<4; mi++) {
        float2 u[8];
#pragma unroll
        for (int nj=0; nj<8; nj++) u[nj] = funpack(acc[mi][nj]);
        float* r0 = P + (size_t)(2*mi)*4096;
        float* r1 = r0 + 4096;
        *(float4*)(r0)     = make_float4(u[0].x,u[1].x,u[2].x,u[3].x);
        *(float4*)(r0 + 4) = make_float4(u[4].x,u[5].x,u[6].x,u[7].x);
        *(float4*)(r1)     = make_float4(u[0].y,u[1].y,u[2].y,u[3].y);
        *(float4*)(r1 + 4) = make_float4(u[4].y,u[5].y,u[6].y,u[7].y);
    }
}

// ---------------- fused epilogues ----------------
__global__ void lstm_red(float* __restrict__ hst, int ldh, float* __restrict__ cst,
                         float* __restrict__ hout, int ldo,
                         const float* __restrict__ bi, const float* __restrict__ bh,
                         const int* __restrict__ kin, int step)
{
    int i = blockIdx.x*256 + threadIdx.x;          // BH
    int b = i >> 10, hh = i & 1023;
    float g[4];
#pragma unroll
    for (int gi=0; gi<4; gi++) {
        int col = (gi<<10) + hh;
        float s = bi[col] + bh[col];
#pragma unroll
        for (int zz=0; zz<KS_GATE; zz++)
            s += g_part[((size_t)(zz*128+b))*4096 + col];
        g[gi] = s;
    }
    float* hp = hst + (size_t)b*ldh + hh;
    float ho = *hp, co = cst[i];
    float cn = sigm(g[1])*co + sigm(g[0])*tanhf(g[2]);
    float hn = sigm(g[3])*tanhf(cn);
    hout[(size_t)b*ldo + hh] = hn;                 // unfrozen output
    bool frozen = step >= kin[b];
    *hp    = frozen ? ho : hn;
    cst[i] = frozen ? co : cn;
}

// attn_core + fused zstep (both consume gen-GEMM partials)
__global__ void attn_core(const float* __restrict__ ctx, float* __restrict__ out,
                          const float* __restrict__ eps,
                          const float* __restrict__ mub, const float* __restrict__ sgb,
                          const int* __restrict__ kin, int step)
{
    __shared__ float sq[H];
    __shared__ float sal[SRC];
    int b = blockIdx.x, t = threadIdx.x;

    if (step >= 0) {                               // fused zstep: Z=256, 256 threads
        int zi = t;
        float m = mub[zi], s = sgb[zi];
#pragma unroll
        for (int zz=0; zz<KS_GEN; zz++) {
            const float* p = g_part + ((size_t)(zz*128+b))*4096;
            m += p[zi];
            s += p[256+zi];
        }
        float zval = m + expf(s) * eps[((size_t)step*B + b)*Z + zi];
        g_x0[(size_t)b*X0LD + zi] = zval;
        bool valid = step < kin[b];
        size_t o = ((size_t)b*KMAX + step)*Z + zi;
        out[o]          = valid ? zval : 0.f;
        out[OUT_MU + o] = valid ? m : 0.f;
        out[OUT_SG + o] = valid ? s : 0.f;
    }

    for (int i=t; i<H; i+=256) {                   // qw reduce (gen cols 512..1535)
        float s = 0.f;
#pragma unroll
        for (int zz=0; zz<KS_GEN; zz++)
            s += g_part[((size_t)(zz*128+b))*4096 + 512 + i];
        sq[i] = s;
    }
    __syncthreads();
    int warp = t>>5, lane = t&31;
#pragma unroll
    for (int s8=0; s8<8; s8++) {
        int s = warp*8 + s8;
        const float* cr = ctx + ((size_t)b*SRC + s)*H;
        float a = 0.f;
        for (int k2=lane; k2<H; k2+=32) a += cr[k2]*sq[k2];
#pragma unroll
        for (int o=16;o>0;o>>=1) a += __shfl_xor_sync(0xffffffffu, a, o);
        if (lane==0) sal[s] = a;
    }
    __syncthreads();
    if (warp==0) {
        float v0 = sal[lane], v1 = sal[lane+32];
        float mx = fmaxf(v0,v1);
#pragma unroll
        for (int o=16;o>0;o>>=1) mx = fmaxf(mx, __shfl_xor_sync(0xffffffffu,mx,o));
        float e0=expf(v0-mx), e1=expf(v1-mx);
        float sm=e0+e1;
#pragma unroll
        for (int o=16;o>0;o>>=1) sm += __shfl_xor_sync(0xffffffffu,sm,o);
        float inv=1.f/sm;
        sal[lane]=e0*inv; sal[lane+32]=e1*inv;
    }
    __syncthreads();
    for (int hh=t; hh<H; hh+=256) {
        float a=0.f;
#pragma unroll 8
        for (int s=0;s<SRC;s++) a += sal[s]*ctx[((size_t)b*SRC+s)*H + hh];
        g_xa[(size_t)b*X1LD + hh] = a;             // weighted -> left half of concat
    }
}

__global__ void attnout_red()
{
    int i = blockIdx.x*256 + threadIdx.x;          // BH
    int b = i>>10, hh = i&1023;
    float s = 0.f;
#pragma unroll
    for (int zz=0; zz<KS_OUT; zz++)
        s += g_part[((size_t)(zz*128+b))*4096 + hh];
    g_x0[(size_t)b*X0LD + 257 + hh] = tanhf(s);
}

// ---------------- prep / init / final ----------------
__global__ void prep_w0(const float* __restrict__ Wih, const float* __restrict__ Whh){
    int i = blockIdx.x*256 + threadIdx.x;
    int r = i / X0LD, c = i - r*X0LD;
    float v;
    if (c < 1281)      v = Wih[(size_t)r*1281 + c];
    else if (c < 1312) v = 0.f;
    else               v = Whh[(size_t)r*1024 + (c-1312)];
    g_w0[i] = v;
}
__global__ void prep_w1(const float* __restrict__ Wih, const float* __restrict__ Whh){
    int i = blockIdx.x*256 + threadIdx.x;
    int r = i >> 11, c = i & 2047;
    g_w1[i] = (c < 1024) ? Wih[(size_t)r*1024 + c] : Whh[(size_t)r*1024 + (c-1024)];
}
__global__ void prep_wg(const float* __restrict__ muW, const float* __restrict__ sgW,
                        const float* __restrict__ aWin){
    int i = blockIdx.x*256 + threadIdx.x;
    int r = i >> 10, c = i & 1023;
    float v;
    if (r < 256)      v = muW[(size_t)r*1024 + c];
    else if (r < 512) v = sgW[(size_t)(r-256)*1024 + c];
    else              v = aWin[(size_t)(r-512)*1024 + c];
    g_wg[i] = v;
}
__global__ void init_a(const float* __restrict__ z0, const int* __restrict__ kin,
                       const float* __restrict__ h0){
    int i = blockIdx.x*256 + threadIdx.x;          // B*X0LD
    int b = i / X0LD, c = i - b*X0LD;
    float v = 0.f;
    if (c < 256)        v = z0[(b<<8) + c];
    else if (c == 256)  v = (float)kin[b];
    else if (c >= 1312) v = h0[(b<<10) + (c-1312)];
    g_x0[i] = v;
}
__global__ void init_b(const float* __restrict__ h0, const float* __restrict__ c0){
    int i = blockIdx.x*256 + threadIdx.x;          // B*X1LD = 2*BH
    int b = i >> 11, c = i & 2047;
    g_x1[i] = (c < 1024) ? 0.f : h0[BH + (b<<10) + (c-1024)];
    g_xa[i] = (c < 1024) ? 0.f : c0[BH + (b<<10) + (c-1024)];   // q = c0[-1] for attn0
    g_c[i]  = c0[i];
}
__global__ void final_copy(float* __restrict__ out){
    int i = blockIdx.x*256 + threadIdx.x;          // BH
    int b = i>>10, hh = i&1023;
    out[OUT_H + i]      = g_x0[(size_t)b*X0LD + 1312 + hh];
    out[OUT_H + BH + i] = g_x1[(size_t)b*X1LD + 1024 + hh];
    out[OUT_C + i]      = g_c[i];
    out[OUT_C + BH + i] = g_c[BH + i];
}

// ---------------- orchestration ----------------
extern "C" void kernel_launch(void* const* d_in, const int* in_sizes, int n_in,
                              void* d_out, int out_size) {
    const float* h0    = (const float*)d_in[0];
    const float* c0    = (const float*)d_in[1];
    const float* ctx   = (const float*)d_in[2];
    const float* z0    = (const float*)d_in[3];
    const int*   kin   = (const int*)  d_in[4];
    const float* eps   = (const float*)d_in[5];
    const float* W_ih0 = (const float*)d_in[6];
    const float* W_hh0 = (const float*)d_in[7];
    const float* b_ih0 = (const float*)d_in[8];
    const float* b_hh0 = (const float*)d_in[9];
    const float* W_ih1 = (const float*)d_in[10];
    const float* W_hh1 = (const float*)d_in[11];
    const float* b_ih1 = (const float*)d_in[12];
    const float* b_hh1 = (const float*)d_in[13];
    const float* aWin  = (const float*)d_in[14];
    const float* aWout = (const float*)d_in[15];
    const float* mu_W  = (const float*)d_in[16];
    const float* mu_b  = (const float*)d_in[17];
    const float* sg_W  = (const float*)d_in[18];
    const float* sg_b  = (const float*)d_in[19];
    float* out = (float*)d_out;

    float *p_x0, *p_x1, *p_xa, *p_c, *p_w0, *p_w1, *p_wg;
    cudaGetSymbolAddress((void**)&p_x0, g_x0);
    cudaGetSymbolAddress((void**)&p_x1, g_x1);
    cudaGetSymbolAddress((void**)&p_xa, g_xa);
    cudaGetSymbolAddress((void**)&p_c,  g_c);
    cudaGetSymbolAddress((void**)&p_w0, g_w0);
    cudaGetSymbolAddress((void**)&p_w1, g_w1);
    cudaGetSymbolAddress((void**)&p_wg, g_wg);

    prep_w0<<<(G4*X0LD)/256, 256>>>(W_ih0, W_hh0);
    prep_w1<<<(G4*X1LD)/256, 256>>>(W_ih1, W_hh1);
    prep_wg<<<(1536*H)/256, 256>>>(mu_W, sg_W, aWin);
    init_a<<<(B*X0LD)/256, 256>>>(z0, kin, h0);
    init_b<<<(B*X1LD)/256, 256>>>(h0, c0);

    // attn0: q = c0[-1] (step=-1 skips fused zstep)
    gemm128<<<dim3(12, KS_GEN), 256>>>(c0 + BH, H, p_wg, H, H);
    attn_core<<<B, 256>>>(ctx, out, eps, mu_b, sg_b, kin, -1);
    gemm128<<<dim3(8, KS_OUT), 256>>>(p_xa, X1LD, aWout, 2*H, 2*H);
    attnout_red<<<BH/256, 256>>>();

    for (int step = 0; step < KMAX; step++) {
        gemm128<<<dim3(32, KS_GATE), 256>>>(p_x0, X0LD, p_w0, X0LD, X0LD);
        lstm_red<<<BH/256, 256>>>(p_x0 + 1312, X0LD, p_c, p_x1, X1LD, b_ih0, b_hh0, kin, step);
        gemm128<<<dim3(32, KS_GATE), 256>>>(p_x1, X1LD, p_w1, X1LD, X1LD);
        lstm_red<<<BH/256, 256>>>(p_x1 + 1024, X1LD, p_c + BH, p_xa + 1024, X1LD, b_ih1, b_hh1, kin, step);
        gemm128<<<dim3(12, KS_GEN), 256>>>(p_xa + 1024, X1LD, p_wg, H, H);
        attn_core<<<B, 256>>>(ctx, out, eps, mu_b, sg_b, kin, step);
        gemm128<<<dim3(8, KS_OUT), 256>>>(p_xa, X1LD, aWout, 2*H, 2*H);
        attnout_red<<<BH/256, 256>>>();
    }

    final_copy<<<BH/256, 256>>>(out);
    (void)in_sizes; (void)n_in; (void)out_size;
}

// round 4
// speedup vs baseline: 1.7740x; 1.7740x over previous
#include <cuda_runtime.h>
#include <math.h>

#define B     128
#define H     1024
#define Z     256
#define SRC   64
#define KMAX  48
#define BH    (B*H)
#define X0LD  2336          // [z(256) | k(1) | attn(1024) | pad(31) | h0(1024)]
#define X1LD  2048          // [h0n | h1]
#define G4    4096
#define KS_GATE 4
#define KS_GEN  12
#define KS_OUT  16

// out layout: z[B,K,Z] | mu | sigma | h_f[2,B,H] | c_f[2,B,H]
#define OUT_MU 1572864
#define OUT_SG 3145728
#define OUT_H  4718592
#define OUT_C  4980736

typedef unsigned long long ull;

// ---------------- device scratch ----------------
__device__ __align__(16) float g_x0[B*X0LD];
__device__ __align__(16) float g_x1[B*X1LD];
__device__ __align__(16) float g_xa[B*X1LD];      // [weighted | q]
__device__ __align__(16) float g_c[2*BH];
__device__ __align__(16) float g_w0[G4*X0LD];     // [W_ih0 | 0pad | W_hh0]
__device__ __align__(16) float g_w1[G4*X1LD];     // [W_ih1 | W_hh1]
__device__ __align__(16) float g_wg[1536*H];      // [mu_W ; sigma_W ; attn_W_in]
__device__ __align__(16) float g_part[16*B*G4];   // split-K partials

// ---------------- packed f32x2 (sm_103a FFMA2) ----------------
__device__ __forceinline__ void dfma2(ull& d, ull a, ull b){
    asm("fma.rn.f32x2 %0, %1, %2, %0;" : "+l"(d) : "l"(a), "l"(b));
}
__device__ __forceinline__ float2 funpack(ull v){
    float2 r; asm("mov.b64 {%0,%1}, %2;" : "=f"(r.x), "=f"(r.y) : "l"(v)); return r;
}
__device__ __forceinline__ float sigm(float x){ return 1.f/(1.f+expf(-x)); }

// ---------------- 128x128-tile split-K GEMM ----------------
// A duplicated in smem (broadcast reads), W plain (n-pairs read as 64-bit lanes).
// Inner loop: 32 FFMA2 + 6 LDS.128 per thread-kk, zero MOVs.
// Partials to g_part[(z*128+m)*4096 + n0+n]. grid=(N/128, KS). K mult of 32.
__global__ __launch_bounds__(256) void gemm128(
    const float* __restrict__ A, int lda,
    const float* __restrict__ W, int ldw, int K)
{
    __shared__ __align__(16) float2 Asd[16][128];   // duplicated (a,a): 16KB
    __shared__ __align__(16) float  Ws[16][128];    // 8KB
    const int t  = threadIdx.x;
    const int n0 = blockIdx.x << 7;
    const int z  = blockIdx.y, KS = gridDim.y;
    const int NU = K >> 5;                 // 32-wide k-units
    const int tm = (t >> 4) << 3;          // 8 m rows
    const int tn = (t & 15) << 3;          // 8 n cols (4 pairs)
    const int lr = t >> 1;                 // loader row 0..127
    const int lk = (t & 1) << 3;           // loader k offset 0/8

    const float* Aptr = A + (size_t)lr * lda + lk;
    const float* Wptr = W + (size_t)(n0 + lr) * ldw + lk;

    ull acc[8][4];
#pragma unroll
    for (int i=0;i<8;i++)
#pragma unroll
        for (int j=0;j<4;j++) acc[i][j]=0ull;

    int cu = z, ch = 0;
    float4 a0r, a1r, w0r, w1r;
    {
        int ko = (cu<<5) + (ch<<4);
        a0r = *(const float4*)(Aptr + ko);
        a1r = *(const float4*)(Aptr + ko + 4);
        w0r = *(const float4*)(Wptr + ko);
        w1r = *(const float4*)(Wptr + ko + 4);
    }
    while (true) {
        __syncthreads();
        Asd[lk+0][lr]=make_float2(a0r.x,a0r.x); Asd[lk+1][lr]=make_float2(a0r.y,a0r.y);
        Asd[lk+2][lr]=make_float2(a0r.z,a0r.z); Asd[lk+3][lr]=make_float2(a0r.w,a0r.w);
        Asd[lk+4][lr]=make_float2(a1r.x,a1r.x); Asd[lk+5][lr]=make_float2(a1r.y,a1r.y);
        Asd[lk+6][lr]=make_float2(a1r.z,a1r.z); Asd[lk+7][lr]=make_float2(a1r.w,a1r.w);
        Ws[lk+0][lr]=w0r.x; Ws[lk+1][lr]=w0r.y; Ws[lk+2][lr]=w0r.z; Ws[lk+3][lr]=w0r.w;
        Ws[lk+4][lr]=w1r.x; Ws[lk+5][lr]=w1r.y; Ws[lk+6][lr]=w1r.z; Ws[lk+7][lr]=w1r.w;
        __syncthreads();
        int nu = cu, nh = ch ^ 1;
        if (nh == 0) nu += KS;
        bool hasNext = (nu < NU);
        if (hasNext) {                     // prefetch next 16-k half during compute
            int ko = (nu<<5) + (nh<<4);
            a0r = *(const float4*)(Aptr + ko);
            a1r = *(const float4*)(Aptr + ko + 4);
            w0r = *(const float4*)(Wptr + ko);
            w1r = *(const float4*)(Wptr + ko + 4);
        }
#pragma unroll
        for (int kk=0; kk<16; kk++) {
            ulonglong2 ad0 = *(const ulonglong2*)&Asd[kk][tm];     // (a,a) pairs, broadcast
            ulonglong2 ad1 = *(const ulonglong2*)&Asd[kk][tm+2];
            ulonglong2 ad2 = *(const ulonglong2*)&Asd[kk][tm+4];
            ulonglong2 ad3 = *(const ulonglong2*)&Asd[kk][tm+6];
            ulonglong2 wq0 = *(const ulonglong2*)&Ws[kk][tn];      // (w_n, w_n+1) pairs
            ulonglong2 wq1 = *(const ulonglong2*)&Ws[kk][tn+4];
#pragma unroll
            for (int mi=0; mi<8; mi++) {
                ull am = (mi==0)?ad0.x:(mi==1)?ad0.y:(mi==2)?ad1.x:(mi==3)?ad1.y:
                         (mi==4)?ad2.x:(mi==5)?ad2.y:(mi==6)?ad3.x:ad3.y;
                dfma2(acc[mi][0], am, wq0.x);
                dfma2(acc[mi][1], am, wq0.y);
                dfma2(acc[mi][2], am, wq1.x);
                dfma2(acc[mi][3], am, wq1.y);
            }
        }
        if (!hasNext) break;
        cu = nu; ch = nh;
    }

    // epilogue: acc[mi][nj] = cols (tn+2nj, tn+2nj+1) of row tm+mi
    float* P = g_part + ((size_t)(z*128 + tm))*4096 + n0 + tn;
#pragma unroll
    for (int mi=0; mi<8; mi++) {
        float2 u0 = funpack(acc[mi][0]);
        float2 u1 = funpack(acc[mi][1]);
        float2 u2 = funpack(acc[mi][2]);
        float2 u3 = funpack(acc[mi][3]);
        float* r = P + (size_t)mi*4096;
        *(float4*)(r)     = make_float4(u0.x,u0.y,u1.x,u1.y);
        *(float4*)(r + 4) = make_float4(u2.x,u2.y,u3.x,u3.y);
    }
}

// ---------------- fused epilogues ----------------
__global__ void lstm_red(float* __restrict__ hst, int ldh, float* __restrict__ cst,
                         float* __restrict__ hout, int ldo,
                         const float* __restrict__ bi, const float* __restrict__ bh,
                         const int* __restrict__ kin, int step)
{
    int i = blockIdx.x*256 + threadIdx.x;          // BH
    int b = i >> 10, hh = i & 1023;
    float g[4];
#pragma unroll
    for (int gi=0; gi<4; gi++) {
        int col = (gi<<10) + hh;
        float s = bi[col] + bh[col];
#pragma unroll
        for (int zz=0; zz<KS_GATE; zz++)
            s += g_part[((size_t)(zz*128+b))*4096 + col];
        g[gi] = s;
    }
    float* hp = hst + (size_t)b*ldh + hh;
    float ho = *hp, co = cst[i];
    float cn = sigm(g[1])*co + sigm(g[0])*tanhf(g[2]);
    float hn = sigm(g[3])*tanhf(cn);
    hout[(size_t)b*ldo + hh] = hn;                 // unfrozen output
    bool frozen = step >= kin[b];
    *hp    = frozen ? ho : hn;
    cst[i] = frozen ? co : cn;
}

// attn_core + fused zstep (both consume gen-GEMM partials)
__global__ void attn_core(const float* __restrict__ ctx, float* __restrict__ out,
                          const float* __restrict__ eps,
                          const float* __restrict__ mub, const float* __restrict__ sgb,
                          const int* __restrict__ kin, int step)
{
    __shared__ float sq[H];
    __shared__ float sal[SRC];
    int b = blockIdx.x, t = threadIdx.x;

    if (step >= 0) {                               // fused zstep: Z=256, 256 threads
        int zi = t;
        float m = mub[zi], s = sgb[zi];
#pragma unroll
        for (int zz=0; zz<KS_GEN; zz++) {
            const float* p = g_part + ((size_t)(zz*128+b))*4096;
            m += p[zi];
            s += p[256+zi];
        }
        float zval = m + expf(s) * eps[((size_t)step*B + b)*Z + zi];
        g_x0[(size_t)b*X0LD + zi] = zval;
        bool valid = step < kin[b];
        size_t o = ((size_t)b*KMAX + step)*Z + zi;
        out[o]          = valid ? zval : 0.f;
        out[OUT_MU + o] = valid ? m : 0.f;
        out[OUT_SG + o] = valid ? s : 0.f;
    }

    for (int i=t; i<H; i+=256) {                   // qw reduce (gen cols 512..1535)
        float s = 0.f;
#pragma unroll
        for (int zz=0; zz<KS_GEN; zz++)
            s += g_part[((size_t)(zz*128+b))*4096 + 512 + i];
        sq[i] = s;
    }
    __syncthreads();
    int warp = t>>5, lane = t&31;
#pragma unroll
    for (int s8=0; s8<8; s8++) {
        int s = warp*8 + s8;
        const float* cr = ctx + ((size_t)b*SRC + s)*H;
        float a = 0.f;
        for (int k2=lane; k2<H; k2+=32) a += cr[k2]*sq[k2];
#pragma unroll
        for (int o=16;o>0;o>>=1) a += __shfl_xor_sync(0xffffffffu, a, o);
        if (lane==0) sal[s] = a;
    }
    __syncthreads();
    if (warp==0) {
        float v0 = sal[lane], v1 = sal[lane+32];
        float mx = fmaxf(v0,v1);
#pragma unroll
        for (int o=16;o>0;o>>=1) mx = fmaxf(mx, __shfl_xor_sync(0xffffffffu,mx,o));
        float e0=expf(v0-mx), e1=expf(v1-mx);
        float sm=e0+e1;
#pragma unroll
        for (int o=16;o>0;o>>=1) sm += __shfl_xor_sync(0xffffffffu,sm,o);
        float inv=1.f/sm;
        sal[lane]=e0*inv; sal[lane+32]=e1*inv;
    }
    __syncthreads();
    for (int hh=t; hh<H; hh+=256) {
        float a=0.f;
#pragma unroll 8
        for (int s=0;s<SRC;s++) a += sal[s]*ctx[((size_t)b*SRC+s)*H + hh];
        g_xa[(size_t)b*X1LD + hh] = a;             // weighted -> left half of concat
    }
}

__global__ void attnout_red()
{
    int i = blockIdx.x*256 + threadIdx.x;          // BH
    int b = i>>10, hh = i&1023;
    float s = 0.f;
#pragma unroll
    for (int zz=0; zz<KS_OUT; zz++)
        s += g_part[((size_t)(zz*128+b))*4096 + hh];
    g_x0[(size_t)b*X0LD + 257 + hh] = tanhf(s);
}

// ---------------- prep / init / final ----------------
__global__ void prep_w0(const float* __restrict__ Wih, const float* __restrict__ Whh){
    int i = blockIdx.x*256 + threadIdx.x;
    int r = i / X0LD, c = i - r*X0LD;
    float v;
    if (c < 1281)      v = Wih[(size_t)r*1281 + c];
    else if (c < 1312) v = 0.f;
    else               v = Whh[(size_t)r*1024 + (c-1312)];
    g_w0[i] = v;
}
__global__ void prep_w1(const float* __restrict__ Wih, const float* __restrict__ Whh){
    int i = blockIdx.x*256 + threadIdx.x;
    int r = i >> 11, c = i & 2047;
    g_w1[i] = (c < 1024) ? Wih[(size_t)r*1024 + c] : Whh[(size_t)r*1024 + (c-1024)];
}
__global__ void prep_wg(const float* __restrict__ muW, const float* __restrict__ sgW,
                        const float* __restrict__ aWin){
    int i = blockIdx.x*256 + threadIdx.x;
    int r = i >> 10, c = i & 1023;
    float v;
    if (r < 256)      v = muW[(size_t)r*1024 + c];
    else if (r < 512) v = sgW[(size_t)(r-256)*1024 + c];
    else              v = aWin[(size_t)(r-512)*1024 + c];
    g_wg[i] = v;
}
__global__ void init_a(const float* __restrict__ z0, const int* __restrict__ kin,
                       const float* __restrict__ h0){
    int i = blockIdx.x*256 + threadIdx.x;          // B*X0LD
    int b = i / X0LD, c = i - b*X0LD;
    float v = 0.f;
    if (c < 256)        v = z0[(b<<8) + c];
    else if (c == 256)  v = (float)kin[b];
    else if (c >= 1312) v = h0[(b<<10) + (c-1312)];
    g_x0[i] = v;
}
__global__ void init_b(const float* __restrict__ h0, const float* __restrict__ c0){
    int i = blockIdx.x*256 + threadIdx.x;          // B*X1LD = 2*BH
    int b = i >> 11, c = i & 2047;
    g_x1[i] = (c < 1024) ? 0.f : h0[BH + (b<<10) + (c-1024)];
    g_xa[i] = (c < 1024) ? 0.f : c0[BH + (b<<10) + (c-1024)];   // q = c0[-1] for attn0
    g_c[i]  = c0[i];
}
__global__ void final_copy(float* __restrict__ out){
    int i = blockIdx.x*256 + threadIdx.x;          // BH
    int b = i>>10, hh = i&1023;
    out[OUT_H + i]      = g_x0[(size_t)b*X0LD + 1312 + hh];
    out[OUT_H + BH + i] = g_x1[(size_t)b*X1LD + 1024 + hh];
    out[OUT_C + i]      = g_c[i];
    out[OUT_C + BH + i] = g_c[BH + i];
}

// ---------------- orchestration ----------------
extern "C" void kernel_launch(void* const* d_in, const int* in_sizes, int n_in,
                              void* d_out, int out_size) {
    const float* h0    = (const float*)d_in[0];
    const float* c0    = (const float*)d_in[1];
    const float* ctx   = (const float*)d_in[2];
    const float* z0    = (const float*)d_in[3];
    const int*   kin   = (const int*)  d_in[4];
    const float* eps   = (const float*)d_in[5];
    const float* W_ih0 = (const float*)d_in[6];
    const float* W_hh0 = (const float*)d_in[7];
    const float* b_ih0 = (const float*)d_in[8];
    const float* b_hh0 = (const float*)d_in[9];
    const float* W_ih1 = (const float*)d_in[10];
    const float* W_hh1 = (const float*)d_in[11];
    const float* b_ih1 = (const float*)d_in[12];
    const float* b_hh1 = (const float*)d_in[13];
    const float* aWin  = (const float*)d_in[14];
    const float* aWout = (const float*)d_in[15];
    const float* mu_W  = (const float*)d_in[16];
    const float* mu_b  = (const float*)d_in[17];
    const float* sg_W  = (const float*)d_in[18];
    const float* sg_b  = (const float*)d_in[19];
    float* out = (float*)d_out;

    float *p_x0, *p_x1, *p_xa, *p_c, *p_w0, *p_w1, *p_wg;
    cudaGetSymbolAddress((void**)&p_x0, g_x0);
    cudaGetSymbolAddress((void**)&p_x1, g_x1);
    cudaGetSymbolAddress((void**)&p_xa, g_xa);
    cudaGetSymbolAddress((void**)&p_c,  g_c);
    cudaGetSymbolAddress((void**)&p_w0, g_w0);
    cudaGetSymbolAddress((void**)&p_w1, g_w1);
    cudaGetSymbolAddress((void**)&p_wg, g_wg);

    prep_w0<<<(G4*X0LD)/256, 256>>>(W_ih0, W_hh0);
    prep_w1<<<(G4*X1LD)/256, 256>>>(W_ih1, W_hh1);
    prep_wg<<<(1536*H)/256, 256>>>(mu_W, sg_W, aWin);
    init_a<<<(B*X0LD)/256, 256>>>(z0, kin, h0);
    init_b<<<(B*X1LD)/256, 256>>>(h0, c0);

    // attn0: q = c0[-1] (step=-1 skips fused zstep)
    gemm128<<<dim3(12, KS_GEN), 256>>>(c0 + BH, H, p_wg, H, H);
    attn_core<<<B, 256>>>(ctx, out, eps, mu_b, sg_b, kin, -1);
    gemm128<<<dim3(8, KS_OUT), 256>>>(p_xa, X1LD, aWout, 2*H, 2*H);
    attnout_red<<<BH/256, 256>>>();

    for (int step = 0; step < KMAX; step++) {
        gemm128<<<dim3(32, KS_GATE), 256>>>(p_x0, X0LD, p_w0, X0LD, X0LD);
        lstm_red<<<BH/256, 256>>>(p_x0 + 1312, X0LD, p_c, p_x1, X1LD, b_ih0, b_hh0, kin, step);
        gemm128<<<dim3(32, KS_GATE), 256>>>(p_x1, X1LD, p_w1, X1LD, X1LD);
        lstm_red<<<BH/256, 256>>>(p_x1 + 1024, X1LD, p_c + BH, p_xa + 1024, X1LD, b_ih1, b_hh1, kin, step);
        gemm128<<<dim3(12, KS_GEN), 256>>>(p_xa + 1024, X1LD, p_wg, H, H);
        attn_core<<<B, 256>>>(ctx, out, eps, mu_b, sg_b, kin, step);
        gemm128<<<dim3(8, KS_OUT), 256>>>(p_xa, X1LD, aWout, 2*H, 2*H);
        attnout_red<<<BH/256, 256>>>();
    }

    final_copy<<<BH/256, 256>>>(out);
    (void)in_sizes; (void)n_in; (void)out_size;
}

// round 6
// speedup vs baseline: 3.7092x; 2.0908x over previous
#include <cuda_runtime.h>
#include <cuda_bf16.h>
#include <math.h>
#include <stdint.h>

#define B     128
#define H     1024
#define Z     256
#define SRC   64
#define KMAX  48
#define BH    (B*H)
#define X0LD  2560          // [z(256) | k(1) | attn(1024) | pad(255) | h0(1024)]
#define X1LD  2048          // [h0n | h1]
#define G4    4096
#define KS_GATE 4
#define KS_GEN  8
#define KS_OUT  16
#define NC0   80            // X0LD/32
#define NC1   64            // X1LD/32
#define NCG   32            // 1024/32
#define NCO   64            // 2048/32

// out layout: z[B,K,Z] | mu | sigma | h_f[2,B,H] | c_f[2,B,H]
#define OUT_MU 1572864
#define OUT_SG 3145728
#define OUT_H  4718592
#define OUT_C  4980736

#define TILEB 4096          // bf16 elements per 128x32 W block (8KB)

// ---------------- device scratch ----------------
__device__ __align__(16) float g_x0[B*X0LD];
__device__ __align__(16) float g_x1[B*X1LD];
__device__ __align__(16) float g_xa[B*X1LD];        // [weighted | q]
__device__ __align__(16) float g_c[2*BH];
__device__ __align__(16) float g_part[16*B*G4];     // split-K partials
// blocked bf16 hi/lo weights: [ntile][chunk][n(128)][k(32)]
__device__ __align__(16) __nv_bfloat16 g_w0h[G4*X0LD], g_w0l[G4*X0LD];
__device__ __align__(16) __nv_bfloat16 g_w1h[G4*X1LD], g_w1l[G4*X1LD];
__device__ __align__(16) __nv_bfloat16 g_wgh[1536*H], g_wgl[1536*H];
__device__ __align__(16) __nv_bfloat16 g_woh[H*2048], g_wol[H*2048];

__device__ __forceinline__ float sigm(float x){ return 1.f/(1.f+expf(-x)); }

__device__ __forceinline__ void mma16816(float* c, const uint32_t* a, const uint32_t* b){
    asm volatile("mma.sync.aligned.m16n8k16.row.col.f32.bf16.bf16.f32 "
        "{%0,%1,%2,%3}, {%4,%5,%6,%7}, {%8,%9}, {%0,%1,%2,%3};"
        : "+f"(c[0]),"+f"(c[1]),"+f"(c[2]),"+f"(c[3])
        : "r"(a[0]),"r"(a[1]),"r"(a[2]),"r"(a[3]), "r"(b[0]),"r"(b[1]));
}

// ---------------- bf16x3 split-K GEMM via mma.sync ----------------
// C_partial = A[128 x K] * W^T, A fp32 row-major, W pre-split hi/lo blocked.
// grid=(N/128, KS). Partials: g_part[(z*128+m)*4096 + n0+n].
__global__ __launch_bounds__(256) void tgemm(
    const float* __restrict__ A, int lda,
    const __nv_bfloat16* __restrict__ Whi, const __nv_bfloat16* __restrict__ Wlo,
    int NCg, int KPS)
{
    __shared__ __align__(16) __nv_bfloat16 sAh[128][40], sAl[128][40];
    __shared__ __align__(16) __nv_bfloat16 sWh[128][40], sWl[128][40];

    const int t = threadIdx.x;
    const int w = t >> 5, lane = t & 31;
    const int g = lane >> 2, tig = lane & 3;
    const int ntile = blockIdx.x, z = blockIdx.y;
    const int n0 = ntile << 7;
    const int mrow = (w & 1) << 6;         // 0 / 64
    const int ncol = (w >> 1) << 5;        // 0..96

    // loader mapping: row = t>>1, half-offset (t&1)*16
    const int lrow = t >> 1;
    const int lofs = (t & 1) << 4;
    const float* aptr = A + (size_t)lrow * lda + lofs + (size_t)(z * KPS) * 32;
    const __nv_bfloat16* whp = Whi + ((size_t)(ntile * NCg + z * KPS) * 128 + lrow) * 32 + lofs;
    const __nv_bfloat16* wlp = Wlo + ((size_t)(ntile * NCg + z * KPS) * 128 + lrow) * 32 + lofs;

    float acc[4][4][4];
#pragma unroll
    for (int i=0;i<4;i++)
#pragma unroll
        for (int j=0;j<4;j++)
#pragma unroll
            for (int q2=0;q2<4;q2++) acc[i][j][q2]=0.f;

    float4 fa0, fa1, fa2, fa3;
    uint4 wh0, wh1, wl0, wl1;
    fa0 = *(const float4*)(aptr);     fa1 = *(const float4*)(aptr+4);
    fa2 = *(const float4*)(aptr+8);   fa3 = *(const float4*)(aptr+12);
    wh0 = *(const uint4*)(whp);       wh1 = *(const uint4*)(whp+8);
    wl0 = *(const uint4*)(wlp);       wl1 = *(const uint4*)(wlp+8);

    for (int ci = 0; ci < KPS; ci++) {
        __syncthreads();
        // split A regs -> hi/lo bf16 and store
        {
            float fv[16] = {fa0.x,fa0.y,fa0.z,fa0.w, fa1.x,fa1.y,fa1.z,fa1.w,
                            fa2.x,fa2.y,fa2.z,fa2.w, fa3.x,fa3.y,fa3.z,fa3.w};
            __nv_bfloat16 hv[16], lv[16];
#pragma unroll
            for (int j=0;j<16;j++){
                hv[j] = __float2bfloat16(fv[j]);
                lv[j] = __float2bfloat16(fv[j] - __bfloat162float(hv[j]));
            }
            *(uint4*)&sAh[lrow][lofs]   = *(uint4*)&hv[0];
            *(uint4*)&sAh[lrow][lofs+8] = *(uint4*)&hv[8];
            *(uint4*)&sAl[lrow][lofs]   = *(uint4*)&lv[0];
            *(uint4*)&sAl[lrow][lofs+8] = *(uint4*)&lv[8];
            *(uint4*)&sWh[lrow][lofs]   = wh0;
            *(uint4*)&sWh[lrow][lofs+8] = wh1;
            *(uint4*)&sWl[lrow][lofs]   = wl0;
            *(uint4*)&sWl[lrow][lofs+8] = wl1;
        }
        __syncthreads();
        if (ci + 1 < KPS) {                // prefetch next chunk
            const float* ap = aptr + (ci+1)*32;
            const __nv_bfloat16* wp1 = whp + (size_t)(ci+1)*TILEB;
            const __nv_bfloat16* wp2 = wlp + (size_t)(ci+1)*TILEB;
            fa0 = *(const float4*)(ap);    fa1 = *(const float4*)(ap+4);
            fa2 = *(const float4*)(ap+8);  fa3 = *(const float4*)(ap+12);
            wh0 = *(const uint4*)(wp1);    wh1 = *(const uint4*)(wp1+8);
            wl0 = *(const uint4*)(wp2);    wl1 = *(const uint4*)(wp2+8);
        }
#pragma unroll
        for (int k16 = 0; k16 < 32; k16 += 16) {
            uint32_t Ah[4][4], Al[4][4], Bh[4][2], Bl[4][2];
            const int kk = k16 + tig*2;
#pragma unroll
            for (int mt=0; mt<4; mt++){
                int r = mrow + mt*16 + g;
                Ah[mt][0] = *(const uint32_t*)&sAh[r][kk];
                Ah[mt][1] = *(const uint32_t*)&sAh[r+8][kk];
                Ah[mt][2] = *(const uint32_t*)&sAh[r][kk+8];
                Ah[mt][3] = *(const uint32_t*)&sAh[r+8][kk+8];
                Al[mt][0] = *(const uint32_t*)&sAl[r][kk];
                Al[mt][1] = *(const uint32_t*)&sAl[r+8][kk];
                Al[mt][2] = *(const uint32_t*)&sAl[r][kk+8];
                Al[mt][3] = *(const uint32_t*)&sAl[r+8][kk+8];
            }
#pragma unroll
            for (int nt=0; nt<4; nt++){
                int r = ncol + nt*8 + g;
                Bh[nt][0] = *(const uint32_t*)&sWh[r][kk];
                Bh[nt][1] = *(const uint32_t*)&sWh[r][kk+8];
                Bl[nt][0] = *(const uint32_t*)&sWl[r][kk];
                Bl[nt][1] = *(const uint32_t*)&sWl[r][kk+8];
            }
#pragma unroll
            for (int mt=0;mt<4;mt++)
#pragma unroll
                for (int nt=0;nt<4;nt++){
                    mma16816(acc[mt][nt], Ah[mt], Bh[nt]);
                    mma16816(acc[mt][nt], Ah[mt], Bl[nt]);
                    mma16816(acc[mt][nt], Al[mt], Bh[nt]);
                }
        }
    }

    // epilogue
#pragma unroll
    for (int mt=0; mt<4; mt++){
        int r0 = mrow + mt*16 + g;
#pragma unroll
        for (int nt=0; nt<4; nt++){
            int col = n0 + ncol + nt*8 + tig*2;
            float* p0 = g_part + ((size_t)(z*128 + r0))*4096 + col;
            float* p1 = g_part + ((size_t)(z*128 + r0 + 8))*4096 + col;
            *(float2*)p0 = make_float2(acc[mt][nt][0], acc[mt][nt][1]);
            *(float2*)p1 = make_float2(acc[mt][nt][2], acc[mt][nt][3]);
        }
    }
}

// ---------------- weight prep: fp32 -> bf16 hi/lo blocked ----------------
__device__ __forceinline__ void put_tile(__nv_bfloat16* hi, __nv_bfloat16* lo,
                                         int NCg, int n, int k, float v){
    int ntile = n >> 7, nin = n & 127, chunk = k >> 5, kin = k & 31;
    size_t d = ((size_t)(ntile * NCg + chunk) * 128 + nin) * 32 + kin;
    __nv_bfloat16 h = __float2bfloat16(v);
    hi[d] = h;
    lo[d] = __float2bfloat16(v - __bfloat162float(h));
}
__global__ void prep0(const float* __restrict__ Wih, const float* __restrict__ Whh){
    int i = blockIdx.x*256 + threadIdx.x;            // G4*X0LD
    int n = i / X0LD, k = i - n*X0LD;
    float v;
    if (k < 1281)      v = Wih[(size_t)n*1281 + k];
    else if (k < 1536) v = 0.f;
    else               v = Whh[(size_t)n*1024 + (k-1536)];
    put_tile(g_w0h, g_w0l, NC0, n, k, v);
}
__global__ void prep1(const float* __restrict__ Wih, const float* __restrict__ Whh){
    int i = blockIdx.x*256 + threadIdx.x;            // G4*X1LD
    int n = i >> 11, k = i & 2047;
    float v = (k < 1024) ? Wih[(size_t)n*1024 + k] : Whh[(size_t)n*1024 + (k-1024)];
    put_tile(g_w1h, g_w1l, NC1, n, k, v);
}
__global__ void prepg(const float* __restrict__ muW, const float* __restrict__ sgW,
                      const float* __restrict__ aWin){
    int i = blockIdx.x*256 + threadIdx.x;            // 1536*H
    int n = i >> 10, k = i & 1023;
    float v;
    if (n < 256)      v = muW[(size_t)n*1024 + k];
    else if (n < 512) v = sgW[(size_t)(n-256)*1024 + k];
    else              v = aWin[(size_t)(n-512)*1024 + k];
    put_tile(g_wgh, g_wgl, NCG, n, k, v);
}
__global__ void prepo(const float* __restrict__ aWout){
    int i = blockIdx.x*256 + threadIdx.x;            // H*2048
    int n = i >> 11, k = i & 2047;
    put_tile(g_woh, g_wol, NCO, n, k, aWout[(size_t)n*2048 + k]);
}

// ---------------- fused epilogues ----------------
__global__ void lstm_red(float* __restrict__ hst, int ldh, float* __restrict__ cst,
                         float* __restrict__ hout, int ldo,
                         const float* __restrict__ bi, const float* __restrict__ bh,
                         const int* __restrict__ kin, int step)
{
    int i = blockIdx.x*256 + threadIdx.x;            // BH
    int b = i >> 10, hh = i & 1023;
    float g[4];
#pragma unroll
    for (int gi=0; gi<4; gi++) {
        int col = (gi<<10) + hh;
        float s = bi[col] + bh[col];
#pragma unroll
        for (int zz=0; zz<KS_GATE; zz++)
            s += g_part[((size_t)(zz*128+b))*4096 + col];
        g[gi] = s;
    }
    float* hp = hst + (size_t)b*ldh + hh;
    float ho = *hp, co = cst[i];
    float cn = sigm(g[1])*co + sigm(g[0])*tanhf(g[2]);
    float hn = sigm(g[3])*tanhf(cn);
    hout[(size_t)b*ldo + hh] = hn;
    bool frozen = step >= kin[b];
    *hp    = frozen ? ho : hn;
    cst[i] = frozen ? co : cn;
}

__global__ void attn_core(const float* __restrict__ ctx, float* __restrict__ out,
                          const float* __restrict__ eps,
                          const float* __restrict__ mub, const float* __restrict__ sgb,
                          const int* __restrict__ kin, int step)
{
    __shared__ float sq[H];
    __shared__ float sal[SRC];
    int b = blockIdx.x, t = threadIdx.x;

    if (step >= 0) {                                 // fused zstep
        int zi = t;
        float m = mub[zi], s = sgb[zi];
#pragma unroll
        for (int zz=0; zz<KS_GEN; zz++) {
            const float* p = g_part + ((size_t)(zz*128+b))*4096;
            m += p[zi];
            s += p[256+zi];
        }
        float zval = m + expf(s) * eps[((size_t)step*B + b)*Z + zi];
        g_x0[(size_t)b*X0LD + zi] = zval;
        bool valid = step < kin[b];
        size_t o = ((size_t)b*KMAX + step)*Z + zi;
        out[o]          = valid ? zval : 0.f;
        out[OUT_MU + o] = valid ? m : 0.f;
        out[OUT_SG + o] = valid ? s : 0.f;
    }

    for (int i=t; i<H; i+=256) {                     // qw reduce (cols 512..1535)
        float s = 0.f;
#pragma unroll
        for (int zz=0; zz<KS_GEN; zz++)
            s += g_part[((size_t)(zz*128+b))*4096 + 512 + i];
        sq[i] = s;
    }
    __syncthreads();
    int warp = t>>5, lane = t&31;
#pragma unroll
    for (int s8=0; s8<8; s8++) {
        int s = warp*8 + s8;
        const float* cr = ctx + ((size_t)b*SRC + s)*H;
        float a = 0.f;
        for (int k2=lane; k2<H; k2+=32) a += cr[k2]*sq[k2];
#pragma unroll
        for (int o=16;o>0;o>>=1) a += __shfl_xor_sync(0xffffffffu, a, o);
        if (lane==0) sal[s] = a;
    }
    __syncthreads();
    if (warp==0) {
        float v0 = sal[lane], v1 = sal[lane+32];
        float mx = fmaxf(v0,v1);
#pragma unroll
        for (int o=16;o>0;o>>=1) mx = fmaxf(mx, __shfl_xor_sync(0xffffffffu,mx,o));
        float e0=expf(v0-mx), e1=expf(v1-mx);
        float sm=e0+e1;
#pragma unroll
        for (int o=16;o>0;o>>=1) sm += __shfl_xor_sync(0xffffffffu,sm,o);
        float inv=1.f/sm;
        sal[lane]=e0*inv; sal[lane+32]=e1*inv;
    }
    __syncthreads();
    for (int hh=t; hh<H; hh+=256) {
        float a=0.f;
#pragma unroll 8
        for (int s=0;s<SRC;s++) a += sal[s]*ctx[((size_t)b*SRC+s)*H + hh];
        g_xa[(size_t)b*X1LD + hh] = a;
    }
}

__global__ void attnout_red()
{
    int i = blockIdx.x*256 + threadIdx.x;            // BH
    int b = i>>10, hh = i&1023;
    float s = 0.f;
#pragma unroll
    for (int zz=0; zz<KS_OUT; zz++)
        s += g_part[((size_t)(zz*128+b))*4096 + hh];
    g_x0[(size_t)b*X0LD + 257 + hh] = tanhf(s);
}

// ---------------- init / final ----------------
__global__ void init_a(const float* __restrict__ z0, const int* __restrict__ kin,
                       const float* __restrict__ h0){
    int i = blockIdx.x*256 + threadIdx.x;            // B*X0LD
    int b = i / X0LD, c = i - b*X0LD;
    float v = 0.f;
    if (c < 256)        v = z0[(b<<8) + c];
    else if (c == 256)  v = (float)kin[b];
    else if (c >= 1536) v = h0[(b<<10) + (c-1536)];
    g_x0[i] = v;
}
__global__ void init_b(const float* __restrict__ h0, const float* __restrict__ c0){
    int i = blockIdx.x*256 + threadIdx.x;            // B*X1LD = 2*BH
    int b = i >> 11, c = i & 2047;
    g_x1[i] = (c < 1024) ? 0.f : h0[BH + (b<<10) + (c-1024)];
    g_xa[i] = (c < 1024) ? 0.f : c0[BH + (b<<10) + (c-1024)];
    g_c[i]  = c0[i];
}
__global__ void final_copy(float* __restrict__ out){
    int i = blockIdx.x*256 + threadIdx.x;            // BH
    int b = i>>10, hh = i&1023;
    out[OUT_H + i]      = g_x0[(size_t)b*X0LD + 1536 + hh];
    out[OUT_H + BH + i] = g_x1[(size_t)b*X1LD + 1024 + hh];
    out[OUT_C + i]      = g_c[i];
    out[OUT_C + BH + i] = g_c[BH + i];
}

// ---------------- orchestration ----------------
extern "C" void kernel_launch(void* const* d_in, const int* in_sizes, int n_in,
                              void* d_out, int out_size) {
    const float* h0    = (const float*)d_in[0];
    const float* c0    = (const float*)d_in[1];
    const float* ctx   = (const float*)d_in[2];
    const float* z0    = (const float*)d_in[3];
    const int*   kin   = (const int*)  d_in[4];
    const float* eps   = (const float*)d_in[5];
    const float* W_ih0 = (const float*)d_in[6];
    const float* W_hh0 = (const float*)d_in[7];
    const float* b_ih0 = (const float*)d_in[8];
    const float* b_hh0 = (const float*)d_in[9];
    const float* W_ih1 = (const float*)d_in[10];
    const float* W_hh1 = (const float*)d_in[11];
    const float* b_ih1 = (const float*)d_in[12];
    const float* b_hh1 = (const float*)d_in[13];
    const float* aWin  = (const float*)d_in[14];
    const float* aWout = (const float*)d_in[15];
    const float* mu_W  = (const float*)d_in[16];
    const float* mu_b  = (const float*)d_in[17];
    const float* sg_W  = (const float*)d_in[18];
    const float* sg_b  = (const float*)d_in[19];
    float* out = (float*)d_out;

    float *p_x0, *p_x1, *p_xa, *p_c;
    __nv_bfloat16 *w0h, *w0l, *w1h, *w1l, *wgh, *wgl, *woh, *wol;
    cudaGetSymbolAddress((void**)&p_x0, g_x0);
    cudaGetSymbolAddress((void**)&p_x1, g_x1);
    cudaGetSymbolAddress((void**)&p_xa, g_xa);
    cudaGetSymbolAddress((void**)&p_c,  g_c);
    cudaGetSymbolAddress((void**)&w0h, g_w0h);
    cudaGetSymbolAddress((void**)&w0l, g_w0l);
    cudaGetSymbolAddress((void**)&w1h, g_w1h);
    cudaGetSymbolAddress((void**)&w1l, g_w1l);
    cudaGetSymbolAddress((void**)&wgh, g_wgh);
    cudaGetSymbolAddress((void**)&wgl, g_wgl);
    cudaGetSymbolAddress((void**)&woh, g_woh);
    cudaGetSymbolAddress((void**)&wol, g_wol);

    prep0<<<(G4*X0LD)/256, 256>>>(W_ih0, W_hh0);
    prep1<<<(G4*X1LD)/256, 256>>>(W_ih1, W_hh1);
    prepg<<<(1536*H)/256, 256>>>(mu_W, sg_W, aWin);
    prepo<<<(H*2048)/256, 256>>>(aWout);
    init_a<<<(B*X0LD)/256, 256>>>(z0, kin, h0);
    init_b<<<(B*X1LD)/256, 256>>>(h0, c0);

    // attn0: q = c0[-1] (step=-1 skips fused zstep)
    tgemm<<<dim3(12, KS_GEN), 256>>>(c0 + BH, H, wgh, wgl, NCG, NCG/KS_GEN);
    attn_core<<<B, 256>>>(ctx, out, eps, mu_b, sg_b, kin, -1);
    tgemm<<<dim3(8, KS_OUT), 256>>>(p_xa, X1LD, woh, wol, NCO, NCO/KS_OUT);
    attnout_red<<<BH/256, 256>>>();

    for (int step = 0; step < KMAX; step++) {
        tgemm<<<dim3(32, KS_GATE), 256>>>(p_x0, X0LD, w0h, w0l, NC0, NC0/KS_GATE);
        lstm_red<<<BH/256, 256>>>(p_x0 + 1536, X0LD, p_c, p_x1, X1LD, b_ih0, b_hh0, kin, step);
        tgemm<<<dim3(32, KS_GATE), 256>>>(p_x1, X1LD, w1h, w1l, NC1, NC1/KS_GATE);
        lstm_red<<<BH/256, 256>>>(p_x1 + 1024, X1LD, p_c + BH, p_xa + 1024, X1LD, b_ih1, b_hh1, kin, step);
        tgemm<<<dim3(12, KS_GEN), 256>>>(p_xa + 1024, X1LD, wgh, wgl, NCG, NCG/KS_GEN);
        attn_core<<<B, 256>>>(ctx, out, eps, mu_b, sg_b, kin, step);
        tgemm<<<dim3(8, KS_OUT), 256>>>(p_xa, X1LD, woh, wol, NCO, NCO/KS_OUT);
        attnout_red<<<BH/256, 256>>>();
    }

    final_copy<<<BH/256, 256>>>(out);
    (void)in_sizes; (void)n_in; (void)out_size;
}